// round 1
// baseline (speedup 1.0000x reference)
#include <cuda_runtime.h>

// Problem dims
#define NI 16384   // inputs
#define NC 4096    // centers
#define ND 256     // dim
#define KK 512     // fused GEMM K = 2*ND

// GEMM tiling
#define BM 128
#define BN 128
#define BK 16
#define PAD 4
#define LDS_ROW (BM + PAD)

// Device scratch (allocation-free rule: __device__ globals)
__device__ float g_A[(size_t)NI * KK];     // 32 MB
__device__ float g_B[(size_t)NC * KK];     // 8 MB
__device__ float g_csum[NC];
__device__ float g_score[NI];

// ---------------------------------------------------------------------------
// Prep A: A[n, d] = x^2, A[n, 256+d] = x
__global__ void prep_A_kernel(const float* __restrict__ x) {
    int idx = blockIdx.x * blockDim.x + threadIdx.x;
    if (idx >= NI * ND) return;
    int n = idx >> 8;        // / 256
    int d = idx & (ND - 1);
    float v = x[idx];
    g_A[(size_t)n * KK + d]      = v * v;
    g_A[(size_t)n * KK + ND + d] = v;
}

// Prep B: one warp per center c.
// B[c, d] = inv2s2;  B[c, 256+d] = -2*centers*inv2s2;  csum[c] = sum c^2*inv2s2
__global__ void prep_B_kernel(const float* __restrict__ centers,
                              const float* __restrict__ sigmas) {
    int warp = (blockIdx.x * blockDim.x + threadIdx.x) >> 5;
    int lane = threadIdx.x & 31;
    if (warp >= NC) return;
    int c = warp;
    float acc = 0.f;
    #pragma unroll
    for (int d = lane; d < ND; d += 32) {
        float s   = sigmas[c * ND + d];
        float ce  = centers[c * ND + d];
        float inv = 1.0f / (2.0f * s * s);
        g_B[(size_t)c * KK + d]      = inv;
        g_B[(size_t)c * KK + ND + d] = -2.0f * ce * inv;
        acc = fmaf(ce * ce, inv, acc);
    }
    #pragma unroll
    for (int m = 16; m; m >>= 1) acc += __shfl_xor_sync(0xffffffffu, acc, m);
    if (lane == 0) g_csum[c] = acc;
}

__global__ void zero_score_kernel() {
    int i = blockIdx.x * blockDim.x + threadIdx.x;
    if (i < NI) g_score[i] = 0.f;
}

// ---------------------------------------------------------------------------
// Main fused kernel: 128x128 tile of d2 = A@B^T, epilogue exp(-d2-csum)*w,
// reduce over the 128 centers of this tile, atomicAdd into g_score[n].
__global__ __launch_bounds__(256)
void rbf_main_kernel(const float* __restrict__ w_lin) {
    __shared__ float As[BK * LDS_ROW];
    __shared__ float Bs[BK * LDS_ROW];

    const int tid = threadIdx.x;
    const int tx  = tid & 15;   // 16 threads across C
    const int ty  = tid >> 4;   // 16 threads across N
    const int bn  = blockIdx.x; // C tile (32)
    const int bm  = blockIdx.y; // N tile (128)

    const float4* Ag = (const float4*)(g_A + (size_t)bm * BM * KK);
    const float4* Bg = (const float4*)(g_B + (size_t)bn * BN * KK);

    // loader mapping: 512 float4s per tile per matrix, 2 per thread
    const int r0 = tid >> 2;   // 0..63 (row), also handles r0+64
    const int c0 = tid & 3;    // which float4 within 16-wide k slab

    float acc[8][8];
    #pragma unroll
    for (int i = 0; i < 8; i++)
        #pragma unroll
        for (int j = 0; j < 8; j++) acc[i][j] = 0.f;

    for (int kt = 0; kt < KK; kt += BK) {
        #pragma unroll
        for (int h = 0; h < 2; h++) {
            int r = r0 + h * 64;
            float4 av = Ag[(size_t)r * (KK / 4) + (kt >> 2) + c0];
            float4 bv = Bg[(size_t)r * (KK / 4) + (kt >> 2) + c0];
            int kb = c0 * 4;
            As[(kb + 0) * LDS_ROW + r] = av.x;
            As[(kb + 1) * LDS_ROW + r] = av.y;
            As[(kb + 2) * LDS_ROW + r] = av.z;
            As[(kb + 3) * LDS_ROW + r] = av.w;
            Bs[(kb + 0) * LDS_ROW + r] = bv.x;
            Bs[(kb + 1) * LDS_ROW + r] = bv.y;
            Bs[(kb + 2) * LDS_ROW + r] = bv.z;
            Bs[(kb + 3) * LDS_ROW + r] = bv.w;
        }
        __syncthreads();

        #pragma unroll
        for (int k = 0; k < BK; k++) {
            float a[8], b[8];
            #pragma unroll
            for (int i = 0; i < 8; i++) a[i] = As[k * LDS_ROW + ty * 8 + i];
            #pragma unroll
            for (int j = 0; j < 8; j++) b[j] = Bs[k * LDS_ROW + tx * 8 + j];
            #pragma unroll
            for (int i = 0; i < 8; i++)
                #pragma unroll
                for (int j = 0; j < 8; j++)
                    acc[i][j] = fmaf(a[i], b[j], acc[i][j]);
        }
        __syncthreads();
    }

    // Epilogue: d2 = acc + csum[c]; v = exp(-d2) * w[c]; reduce over c.
    const int cb = bn * BN + tx * 8;
    float cs[8], wv[8];
    #pragma unroll
    for (int j = 0; j < 8; j++) {
        cs[j] = g_csum[cb + j];
        wv[j] = w_lin[cb + j];
    }

    #pragma unroll
    for (int i = 0; i < 8; i++) {
        float s = 0.f;
        #pragma unroll
        for (int j = 0; j < 8; j++) {
            float d2 = acc[i][j] + cs[j];
            s = fmaf(__expf(-d2), wv[j], s);
        }
        // reduce across the 16 tx lanes (lanes sharing ty within the warp)
        #pragma unroll
        for (int m = 8; m; m >>= 1) s += __shfl_xor_sync(0xffffffffu, s, m);
        if (tx == 0) atomicAdd(&g_score[bm * BM + ty * 8 + i], s);
    }
}

__global__ void finalize_kernel(const float* __restrict__ b_lin,
                                float* __restrict__ out) {
    int n = blockIdx.x * blockDim.x + threadIdx.x;
    if (n < NI) {
        float s = g_score[n] + b_lin[0];
        out[n] = 1.0f / (1.0f + __expf(-s));
    }
}

// ---------------------------------------------------------------------------
extern "C" void kernel_launch(void* const* d_in, const int* in_sizes, int n_in,
                              void* d_out, int out_size) {
    const float* x       = (const float*)d_in[0];
    const float* centers = (const float*)d_in[1];
    const float* sigmas  = (const float*)d_in[2];
    const float* w_lin   = (const float*)d_in[3];
    const float* b_lin   = (const float*)d_in[4];
    float* out = (float*)d_out;

    prep_A_kernel<<<(NI * ND + 255) / 256, 256>>>(x);
    prep_B_kernel<<<(NC * 32 + 255) / 256, 256>>>(centers, sigmas);
    zero_score_kernel<<<NI / 256, 256>>>();
    dim3 grid(NC / BN, NI / BM);  // (32, 128)
    rbf_main_kernel<<<grid, 256>>>(w_lin);
    finalize_kernel<<<NI / 256, 256>>>(b_lin, out);
}

// round 3
// speedup vs baseline: 6.9059x; 6.9059x over previous
#include <cuda_runtime.h>
#include <cuda_bf16.h>
#include <cstdint>

// Problem dims
#define NI 16384
#define NC 4096
#define ND 256
#define KK 512          // fused GEMM K

// Tiling
#define BM 128
#define BN 128
#define BK 64           // bf16 elems per stage
#define KITERS (KK / BK)    // 8
#define ROWB 144            // padded row stride bytes (64*2 + 16), conflict-free
#define TILE_BYTES (128 * ROWB)          // 18432
#define STAGE_BYTES (2 * TILE_BYTES)     // A + B
#define SM_A(st) ((st) * STAGE_BYTES)
#define SM_B(st) ((st) * STAGE_BYTES + TILE_BYTES)
#define SMEM_BYTES (2 * STAGE_BYTES)     // 73728

// Device scratch (allocation-free rule)
__device__ __nv_bfloat16 g_A[(size_t)NI * KK];   // [x^2 | x]
__device__ __nv_bfloat16 g_B[(size_t)NC * KK];   // [inv2s2 | -2c*inv2s2]
__device__ float g_csum[NC];
__device__ float g_score[NI];

// ---------------------------------------------------------------- helpers
__device__ __forceinline__ uint32_t smem_u32(const void* p) {
    uint32_t a;
    asm("{ .reg .u64 t; cvta.to.shared.u64 t, %1; cvt.u32.u64 %0, t; }" : "=r"(a) : "l"(p));
    return a;
}
#define CP_ASYNC16(dst, src) \
    asm volatile("cp.async.cg.shared.global [%0], [%1], 16;" :: "r"(dst), "l"(src) : "memory")
#define CP_COMMIT() asm volatile("cp.async.commit_group;" ::: "memory")

__device__ __forceinline__ void ldm_x4(uint32_t* r, uint32_t addr) {
    asm volatile("ldmatrix.sync.aligned.m8n8.x4.shared.b16 {%0,%1,%2,%3}, [%4];"
                 : "=r"(r[0]), "=r"(r[1]), "=r"(r[2]), "=r"(r[3]) : "r"(addr));
}
__device__ __forceinline__ void ldm_x2(uint32_t* r, uint32_t addr) {
    asm volatile("ldmatrix.sync.aligned.m8n8.x2.shared.b16 {%0,%1}, [%2];"
                 : "=r"(r[0]), "=r"(r[1]) : "r"(addr));
}
__device__ __forceinline__ void mma_bf16(float* c, const uint32_t* a, const uint32_t* b) {
    asm volatile(
        "mma.sync.aligned.m16n8k16.row.col.f32.bf16.bf16.f32 "
        "{%0,%1,%2,%3}, {%4,%5,%6,%7}, {%8,%9}, {%0,%1,%2,%3};"
        : "+f"(c[0]), "+f"(c[1]), "+f"(c[2]), "+f"(c[3])
        : "r"(a[0]), "r"(a[1]), "r"(a[2]), "r"(a[3]), "r"(b[0]), "r"(b[1]));
}

// ---------------------------------------------------------------- prep kernels
__global__ void prep_A_kernel(const float* __restrict__ x) {
    int idx = blockIdx.x * blockDim.x + threadIdx.x;
    if (idx >= NI * ND) return;
    int n = idx >> 8;
    int d = idx & (ND - 1);
    float v = x[idx];
    g_A[(size_t)n * KK + d]      = __float2bfloat16(v * v);
    g_A[(size_t)n * KK + ND + d] = __float2bfloat16(v);
}

__global__ void prep_B_kernel(const float* __restrict__ centers,
                              const float* __restrict__ sigmas) {
    int warp = (blockIdx.x * blockDim.x + threadIdx.x) >> 5;
    int lane = threadIdx.x & 31;
    if (warp >= NC) return;
    int c = warp;
    float acc = 0.f;
    #pragma unroll
    for (int d = lane; d < ND; d += 32) {
        float s   = sigmas[c * ND + d];
        float ce  = centers[c * ND + d];
        float inv = 1.0f / (2.0f * s * s);
        g_B[(size_t)c * KK + d]      = __float2bfloat16(inv);
        g_B[(size_t)c * KK + ND + d] = __float2bfloat16(-2.0f * ce * inv);
        acc = fmaf(ce * ce, inv, acc);
    }
    #pragma unroll
    for (int m = 16; m; m >>= 1) acc += __shfl_xor_sync(0xffffffffu, acc, m);
    if (lane == 0) g_csum[c] = acc;
}

__global__ void zero_score_kernel() {
    int i = blockIdx.x * blockDim.x + threadIdx.x;
    if (i < NI) g_score[i] = 0.f;
}

// ---------------------------------------------------------------- main kernel
__global__ void __launch_bounds__(256, 2)
rbf_mma_kernel(const float* __restrict__ w_lin) {
    extern __shared__ char smem[];
    const uint32_t smem_base = smem_u32(smem);
    const int tid  = threadIdx.x;
    const int lane = tid & 31;
    const int wid  = tid >> 5;
    const int wm   = wid >> 2;      // 0..1  (M)
    const int wn   = wid & 3;       // 0..3  (N)
    const int bn   = blockIdx.x;    // center tile
    const int bm   = blockIdx.y;    // input tile

    const char* gA = (const char*)g_A;
    const char* gB = (const char*)g_B;

    auto load_stage = [&](int st, int kiter) {
        const uint32_t baseA = smem_base + SM_A(st);
        const uint32_t baseB = smem_base + SM_B(st);
        const size_t koffB = (size_t)kiter * BK * 2;  // byte offset along K
        #pragma unroll
        for (int i = 0; i < 4; i++) {
            int idx = tid + i * 256;        // 0..1023
            int row = idx >> 3, ch = idx & 7;
            uint64_t srcA = __cvta_generic_to_global(
                gA + ((size_t)(bm * BM + row) * KK) * 2 + koffB + ch * 16);
            CP_ASYNC16(baseA + row * ROWB + ch * 16, srcA);
            uint64_t srcB = __cvta_generic_to_global(
                gB + ((size_t)(bn * BN + row) * KK) * 2 + koffB + ch * 16);
            CP_ASYNC16(baseB + row * ROWB + ch * 16, srcB);
        }
        CP_COMMIT();
    };

    float acc[4][4][4];
    #pragma unroll
    for (int mt = 0; mt < 4; mt++)
        #pragma unroll
        for (int nt = 0; nt < 4; nt++)
            #pragma unroll
            for (int e = 0; e < 4; e++) acc[mt][nt][e] = 0.f;

    load_stage(0, 0);

    #pragma unroll 1
    for (int k = 0; k < KITERS; k++) {
        const int st = k & 1;
        if (k + 1 < KITERS) {
            load_stage(st ^ 1, k + 1);
            asm volatile("cp.async.wait_group 1;" ::: "memory");
        } else {
            asm volatile("cp.async.wait_group 0;" ::: "memory");
        }
        __syncthreads();

        const uint32_t aBase = smem_base + SM_A(st);
        const uint32_t bBase = smem_base + SM_B(st);
        #pragma unroll
        for (int kc = 0; kc < 4; kc++) {           // 4 x k16 per stage
            uint32_t a[4][4], b[4][2];
            #pragma unroll
            for (int mt = 0; mt < 4; mt++) {
                int row = wm * 64 + mt * 16 + (lane & 15);
                uint32_t addr = aBase + row * ROWB + (kc * 16 + ((lane >> 4) << 3)) * 2;
                ldm_x4(a[mt], addr);
            }
            #pragma unroll
            for (int nt = 0; nt < 4; nt++) {
                int row = wn * 32 + nt * 8 + (lane & 7);
                uint32_t addr = bBase + row * ROWB + (kc * 16 + (((lane >> 3) & 1) << 3)) * 2;
                ldm_x2(b[nt], addr);
            }
            #pragma unroll
            for (int mt = 0; mt < 4; mt++)
                #pragma unroll
                for (int nt = 0; nt < 4; nt++)
                    mma_bf16(acc[mt][nt], a[mt], b[nt]);
        }
        __syncthreads();
    }

    // ---------------- epilogue: d2 = acc + csum; add exp(-d2)*w only if d2<60
    const int cBase = bn * BN + wn * 32;
    float cs[4][2], wv[4][2];
    #pragma unroll
    for (int nt = 0; nt < 4; nt++)
        #pragma unroll
        for (int j = 0; j < 2; j++) {
            int c = cBase + nt * 8 + (lane & 3) * 2 + j;
            cs[nt][j] = __ldg(&g_csum[c]);
            wv[nt][j] = __ldg(&w_lin[c]);
        }

    float mn = 1e30f;
    #pragma unroll
    for (int mt = 0; mt < 4; mt++)
        #pragma unroll
        for (int nt = 0; nt < 4; nt++)
            #pragma unroll
            for (int e = 0; e < 4; e++)
                mn = fminf(mn, acc[mt][nt][e] + cs[nt][e & 1]);

    if (__any_sync(0xffffffffu, mn < 60.f)) {       // rare path
        float rs[4][2];
        #pragma unroll
        for (int mt = 0; mt < 4; mt++) { rs[mt][0] = 0.f; rs[mt][1] = 0.f; }
        #pragma unroll
        for (int mt = 0; mt < 4; mt++)
            #pragma unroll
            for (int nt = 0; nt < 4; nt++)
                #pragma unroll
                for (int e = 0; e < 4; e++) {
                    float d2 = acc[mt][nt][e] + cs[nt][e & 1];
                    if (d2 < 60.f)
                        rs[mt][e >> 1] = fmaf(__expf(-d2), wv[nt][e & 1], rs[mt][e >> 1]);
                }
        #pragma unroll
        for (int mt = 0; mt < 4; mt++)
            #pragma unroll
            for (int h = 0; h < 2; h++) {
                float v = rs[mt][h];
                v += __shfl_xor_sync(0xffffffffu, v, 1);
                v += __shfl_xor_sync(0xffffffffu, v, 2);
                if ((lane & 3) == 0)
                    atomicAdd(&g_score[bm * BM + wm * 64 + mt * 16 + h * 8 + (lane >> 2)], v);
            }
    }
    // fast path: contributions are 0; g_score pre-zeroed -> nothing to do
}

__global__ void finalize_kernel(const float* __restrict__ b_lin,
                                float* __restrict__ out) {
    int n = blockIdx.x * blockDim.x + threadIdx.x;
    if (n < NI) {
        float s = g_score[n] + b_lin[0];
        out[n] = 1.0f / (1.0f + __expf(-s));
    }
}

// ---------------------------------------------------------------- launch
extern "C" void kernel_launch(void* const* d_in, const int* in_sizes, int n_in,
                              void* d_out, int out_size) {
    const float* x       = (const float*)d_in[0];
    const float* centers = (const float*)d_in[1];
    const float* sigmas  = (const float*)d_in[2];
    const float* w_lin   = (const float*)d_in[3];
    const float* b_lin   = (const float*)d_in[4];
    float* out = (float*)d_out;

    cudaFuncSetAttribute(rbf_mma_kernel,
                         cudaFuncAttributeMaxDynamicSharedMemorySize, SMEM_BYTES);

    prep_A_kernel<<<(NI * ND + 255) / 256, 256>>>(x);
    prep_B_kernel<<<(NC * 32 + 255) / 256, 256>>>(centers, sigmas);
    zero_score_kernel<<<NI / 256, 256>>>();
    dim3 grid(NC / BN, NI / BM);   // (32, 128)
    rbf_mma_kernel<<<grid, 256, SMEM_BYTES>>>(w_lin);
    finalize_kernel<<<NI / 256, 256>>>(b_lin, out);
}